// round 6
// baseline (speedup 1.0000x reference)
#include <cuda_runtime.h>
#include <cuda_bf16.h>

// ============================================================================
// MaskFunctionHaar fused kernel, v3.
// Output depends only on M = floor(t*1024) in [0,1024) (all Haar edges are
// exact fp32 multiples of 2^-10). 1024 threads/block: thread tid builds LUT
// entry M=tid with a lean single-eval MLP tail (regs <= 64 so all 32 warps
// fit -> 8 warps/SMSP for latency hiding), then gathers one float4 of t.
// Grid = 32 blocks covers all 32768 float4 samples.
// ============================================================================

__global__ __launch_bounds__(1024, 1) void haar_fused3_kernel(
    const float4* __restrict__ t4,
    const float* __restrict__ W1, const float* __restrict__ b1,
    const float* __restrict__ W2, const float* __restrict__ b2,
    const float* __restrict__ W3, const float* __restrict__ b3,
    float4* __restrict__ out4, int n4) {
    __shared__ float4 lut[1024];     // 16 KB
    __shared__ float4 sW2v[16];      // W2 rows, 2 float4 per row
    __shared__ float4 sW3v[8];       // W3 rows padded to float4
    __shared__ float  sb1[8];
    __shared__ float4 sb2v[2];
    __shared__ float4 sb3v;
    __shared__ float  w3raw[24];

    const int tid = threadIdx.x;
    const int g   = blockIdx.x * 1024 + tid;

    // prefetch this thread's t values (hide DRAM latency under LUT build)
    float4 tv = (g < n4) ? __ldg(t4 + g) : make_float4(0.f, 0.f, 0.f, 0.f);

    // ---- stage weights into SMEM ----
    if (tid < 16) {
        sW2v[tid] = __ldg((const float4*)W2 + tid);
    } else if (tid < 40) {               // W3: 24 coalesced scalar loads
        w3raw[tid - 16] = __ldg(W3 + (tid - 16));
    } else if (tid < 48) {
        sb1[tid - 40] = __ldg(b1 + (tid - 40));
    } else if (tid < 56) {
        ((float*)sb2v)[tid - 48] = __ldg(b2 + (tid - 48));
    } else if (tid < 59) {
        ((float*)&sb3v)[tid - 56] = __ldg(b3 + (tid - 56));
    } else if (tid == 59) {
        ((float*)&sb3v)[3] = 0.0f;
    }
    __syncthreads();
    if (tid < 8) {                        // repack W3 rows into padded float4
        sW3v[tid] = make_float4(w3raw[tid * 3], w3raw[tid * 3 + 1],
                                w3raw[tid * 3 + 2], 0.0f);
    }
    __syncthreads();

    // ---- layer 1: M = tid, 10 Haar levels ----
    float P[8];
#pragma unroll
    for (int h = 0; h < 8; ++h) P[h] = sb1[h];

#pragma unroll
    for (int j = 0; j < 10; ++j) {
        int idx = (1 << j) - 1 + (tid >> (10 - j));
        float s = ((tid >> (9 - j)) & 1) ? -1.0f : 1.0f;
        const float4* row = (const float4*)(W1 + idx * 8);
        float4 a = __ldg(row);
        float4 c = __ldg(row + 1);
        P[0] = fmaf(s, a.x, P[0]); P[1] = fmaf(s, a.y, P[1]);
        P[2] = fmaf(s, a.z, P[2]); P[3] = fmaf(s, a.w, P[3]);
        P[4] = fmaf(s, c.x, P[4]); P[5] = fmaf(s, c.y, P[5]);
        P[6] = fmaf(s, c.z, P[6]); P[7] = fmaf(s, c.w, P[7]);
    }
#pragma unroll
    for (int h = 0; h < 8; ++h) P[h] = fmaxf(P[h], 0.0f);   // h1 in place

    // ---- layer 2: h2 = relu(h1 @ W2 + b2) ----
    float h2[8];
    {
        float4 bb0 = sb2v[0], bb1 = sb2v[1];
        h2[0] = bb0.x; h2[1] = bb0.y; h2[2] = bb0.z; h2[3] = bb0.w;
        h2[4] = bb1.x; h2[5] = bb1.y; h2[6] = bb1.z; h2[7] = bb1.w;
    }
#pragma unroll
    for (int h = 0; h < 8; ++h) {
        float4 w0 = sW2v[2 * h];
        float4 w1 = sW2v[2 * h + 1];
        float x = P[h];
        h2[0] = fmaf(x, w0.x, h2[0]); h2[1] = fmaf(x, w0.y, h2[1]);
        h2[2] = fmaf(x, w0.z, h2[2]); h2[3] = fmaf(x, w0.w, h2[3]);
        h2[4] = fmaf(x, w1.x, h2[4]); h2[5] = fmaf(x, w1.y, h2[5]);
        h2[6] = fmaf(x, w1.z, h2[6]); h2[7] = fmaf(x, w1.w, h2[7]);
    }
#pragma unroll
    for (int k = 0; k < 8; ++k) h2[k] = fmaxf(h2[k], 0.0f);

    // ---- layer 3 ----
    float4 o = sb3v;
#pragma unroll
    for (int k = 0; k < 8; ++k) {
        float4 w = sW3v[k];
        float x = h2[k];
        o.x = fmaf(x, w.x, o.x);
        o.y = fmaf(x, w.y, o.y);
        o.z = fmaf(x, w.z, o.z);
    }
    o.w = 0.0f;
    lut[tid] = o;

    __syncthreads();

    // ---- gather: one float4 of t -> 4 SMEM lookups -> 3 float4 stores ----
    if (g < n4) {
        unsigned m0 = min((unsigned)(int)(tv.x * 1024.0f), 1023u);
        unsigned m1 = min((unsigned)(int)(tv.y * 1024.0f), 1023u);
        unsigned m2 = min((unsigned)(int)(tv.z * 1024.0f), 1023u);
        unsigned m3 = min((unsigned)(int)(tv.w * 1024.0f), 1023u);

        float4 r0 = lut[m0];
        float4 r1 = lut[m1];
        float4 r2 = lut[m2];
        float4 r3 = lut[m3];

        out4[g * 3 + 0] = make_float4(r0.x, r0.y, r0.z, r1.x);
        out4[g * 3 + 1] = make_float4(r1.y, r1.z, r2.x, r2.y);
        out4[g * 3 + 2] = make_float4(r2.z, r3.x, r3.y, r3.z);
    }
}

extern "C" void kernel_launch(void* const* d_in, const int* in_sizes, int n_in,
                              void* d_out, int out_size) {
    const float* t  = (const float*)d_in[0];
    const float* W1 = (const float*)d_in[1];
    const float* b1 = (const float*)d_in[2];
    const float* W2 = (const float*)d_in[3];
    const float* b2 = (const float*)d_in[4];
    const float* W3 = (const float*)d_in[5];
    const float* b3 = (const float*)d_in[6];
    float* out = (float*)d_out;

    int n  = in_sizes[0];             // B*T = 131072
    int n4 = n / 4;                   // 32768 float4 samples
    int grid = (n4 + 1023) / 1024;    // 32 blocks, 1 float4 per thread

    haar_fused3_kernel<<<grid, 1024>>>(
        (const float4*)t, W1, b1, W2, b2, W3, b3, (float4*)out, n4);
}

// round 10
// speedup vs baseline: 1.2921x; 1.2921x over previous
#include <cuda_runtime.h>
#include <cuda_bf16.h>

// ============================================================================
// MaskFunctionHaar fused kernel, v4.1.
// Output depends only on M = floor(t*1024) in [0,1024). Each block (256 thr)
// builds the 1024-entry float4 LUT in SMEM: thread tid owns M in
// {4*tid..4*tid+3} (levels 0..7 shared partial P, level 8 row +/-, level 9
// one of two rows). MLP tail weights (W2, W3, b2, b3) live in REGISTERS
// (uniform __ldg broadcasts) -- zero LDS in the tails. Then each thread
// gathers one float4 of t -> 3 coalesced float4 stores.
// ============================================================================

__global__ __launch_bounds__(256, 1) void haar_fused4_kernel(
    const float4* __restrict__ t4,
    const float* __restrict__ W1, const float* __restrict__ b1,
    const float* __restrict__ W2, const float* __restrict__ b2,
    const float* __restrict__ W3, const float* __restrict__ b3,
    float4* __restrict__ out4, int n4) {
    __shared__ float4 lut[1024];     // 16 KB

    const int tid = threadIdx.x;
    const int g   = blockIdx.x * 256 + tid;

    // prefetch this thread's t values (hide DRAM latency under LUT build)
    float4 tv = (g < n4) ? __ldg(t4 + g) : make_float4(0.f, 0.f, 0.f, 0.f);

    // ---- stage tail weights into REGISTERS (uniform broadcast loads) ----
    float w2[64];
#pragma unroll
    for (int i = 0; i < 16; ++i) {
        float4 v = __ldg((const float4*)W2 + i);
        w2[4 * i + 0] = v.x; w2[4 * i + 1] = v.y;
        w2[4 * i + 2] = v.z; w2[4 * i + 3] = v.w;
    }
    float w3[24];
#pragma unroll
    for (int i = 0; i < 6; ++i) {
        float4 v = __ldg((const float4*)W3 + i);
        w3[4 * i + 0] = v.x; w3[4 * i + 1] = v.y;
        w3[4 * i + 2] = v.z; w3[4 * i + 3] = v.w;
    }
    float bb2[8];
    {
        float4 v0 = __ldg((const float4*)b2);
        float4 v1 = __ldg((const float4*)b2 + 1);
        bb2[0] = v0.x; bb2[1] = v0.y; bb2[2] = v0.z; bb2[3] = v0.w;
        bb2[4] = v1.x; bb2[5] = v1.y; bb2[6] = v1.z; bb2[7] = v1.w;
    }
    float bb3[3];
    bb3[0] = __ldg(b3 + 0); bb3[1] = __ldg(b3 + 1); bb3[2] = __ldg(b3 + 2);

    // ---- layer 1 shared prefix: levels 0..7 depend only on tid (= M>>2) ----
    float P[8];
    {
        float4 v0 = __ldg((const float4*)b1);
        float4 v1 = __ldg((const float4*)b1 + 1);
        P[0] = v0.x; P[1] = v0.y; P[2] = v0.z; P[3] = v0.w;
        P[4] = v1.x; P[5] = v1.y; P[6] = v1.z; P[7] = v1.w;
    }
#pragma unroll
    for (int j = 0; j < 8; ++j) {
        int idx = (1 << j) - 1 + (tid >> (8 - j));
        float s = ((tid >> (7 - j)) & 1) ? -1.0f : 1.0f;
        const float4* row = (const float4*)(W1 + idx * 8);
        float4 a = __ldg(row);
        float4 c = __ldg(row + 1);
        P[0] = fmaf(s, a.x, P[0]); P[1] = fmaf(s, a.y, P[1]);
        P[2] = fmaf(s, a.z, P[2]); P[3] = fmaf(s, a.w, P[3]);
        P[4] = fmaf(s, c.x, P[4]); P[5] = fmaf(s, c.y, P[5]);
        P[6] = fmaf(s, c.z, P[6]); P[7] = fmaf(s, c.w, P[7]);
    }

    // level 8 row (sign = bit1 of M), level 9 rows (sign = bit0 of M)
    const float4* r8 = (const float4*)(W1 + (255 + tid) * 8);
    const float4* ra = (const float4*)(W1 + (511 + 2 * tid) * 8);
    const float4* rb = (const float4*)(W1 + (512 + 2 * tid) * 8);
    float4 e8a = __ldg(r8), e8c = __ldg(r8 + 1);
    float4 aA = __ldg(ra), cA = __ldg(ra + 1);
    float4 aB = __ldg(rb), cB = __ldg(rb + 1);

    float E8[8] = {e8a.x, e8a.y, e8a.z, e8a.w, e8c.x, e8c.y, e8c.z, e8c.w};
    float RA[8] = {aA.x, aA.y, aA.z, aA.w, cA.x, cA.y, cA.z, cA.w};
    float RB[8] = {aB.x, aB.y, aB.z, aB.w, cB.x, cB.y, cB.z, cB.w};

    // four preactivations (straight-line; relu applied here)
    float h10[8], h11[8], h12[8], h13[8];
#pragma unroll
    for (int h = 0; h < 8; ++h) {
        float qp = P[h] + E8[h];
        float qn = P[h] - E8[h];
        h10[h] = fmaxf(qp + RA[h], 0.0f);   // M = 4*tid
        h11[h] = fmaxf(qp - RA[h], 0.0f);   // M = 4*tid+1
        h12[h] = fmaxf(qn + RB[h], 0.0f);   // M = 4*tid+2
        h13[h] = fmaxf(qn - RB[h], 0.0f);   // M = 4*tid+3
    }

    // ---- 4 MLP tails, weights in registers (no LDS at all) ----
    const float* h1s[4] = {h10, h11, h12, h13};
#pragma unroll
    for (int e = 0; e < 4; ++e) {
        const float* h1 = h1s[e];

        float h2[8];
#pragma unroll
        for (int k = 0; k < 8; ++k) h2[k] = bb2[k];
#pragma unroll
        for (int h = 0; h < 8; ++h) {
            float x = h1[h];
#pragma unroll
            for (int k = 0; k < 8; ++k) h2[k] = fmaf(x, w2[h * 8 + k], h2[k]);
        }
#pragma unroll
        for (int k = 0; k < 8; ++k) h2[k] = fmaxf(h2[k], 0.0f);

        float o0 = bb3[0], o1 = bb3[1], o2 = bb3[2];
#pragma unroll
        for (int k = 0; k < 8; ++k) {
            float x = h2[k];
            o0 = fmaf(x, w3[k * 3 + 0], o0);
            o1 = fmaf(x, w3[k * 3 + 1], o1);
            o2 = fmaf(x, w3[k * 3 + 2], o2);
        }
        lut[4 * tid + e] = make_float4(o0, o1, o2, 0.0f);
    }

    __syncthreads();

    // ---- gather: one float4 of t -> 4 SMEM lookups -> 3 float4 stores ----
    if (g < n4) {
        unsigned m0 = min((unsigned)(int)(tv.x * 1024.0f), 1023u);
        unsigned m1 = min((unsigned)(int)(tv.y * 1024.0f), 1023u);
        unsigned m2 = min((unsigned)(int)(tv.z * 1024.0f), 1023u);
        unsigned m3 = min((unsigned)(int)(tv.w * 1024.0f), 1023u);

        float4 r0 = lut[m0];
        float4 r1 = lut[m1];
        float4 r2 = lut[m2];
        float4 r3 = lut[m3];

        out4[g * 3 + 0] = make_float4(r0.x, r0.y, r0.z, r1.x);
        out4[g * 3 + 1] = make_float4(r1.y, r1.z, r2.x, r2.y);
        out4[g * 3 + 2] = make_float4(r2.z, r3.x, r3.y, r3.z);
    }
}

extern "C" void kernel_launch(void* const* d_in, const int* in_sizes, int n_in,
                              void* d_out, int out_size) {
    const float* t  = (const float*)d_in[0];
    const float* W1 = (const float*)d_in[1];
    const float* b1 = (const float*)d_in[2];
    const float* W2 = (const float*)d_in[3];
    const float* b2 = (const float*)d_in[4];
    const float* W3 = (const float*)d_in[5];
    const float* b3 = (const float*)d_in[6];
    float* out = (float*)d_out;

    int n  = in_sizes[0];            // B*T = 131072
    int n4 = n / 4;                  // 32768 float4 samples
    int grid = (n4 + 255) / 256;     // 128 blocks, 1 float4 per thread

    haar_fused4_kernel<<<grid, 256>>>(
        (const float4*)t, W1, b1, W2, b2, W3, b3, (float4*)out, n4);
}

// round 11
// speedup vs baseline: 1.3168x; 1.0191x over previous
#include <cuda_runtime.h>
#include <cuda_bf16.h>

// ============================================================================
// MaskFunctionHaar, v5: global-LUT two-kernel split.
// Output depends only on M = floor(t*1024) in [0,1024) (Haar edges are exact
// fp32 multiples of 2^-10).
//   Kernel A (prep): 32 blocks x 32 threads, one M per thread, computes the
//     MLP into a global 1024 x float4 LUT. Weights live in registers.
//   Kernel B (apply): 128 blocks x 256 threads. Each block copies the 16KB
//     LUT gmem->smem (coalesced LDG.128, L2-resident), then each thread
//     gathers one float4 of t -> 4 SMEM lookups -> 3 coalesced float4 stores.
// ============================================================================

__device__ float4 g_lut[1024];

__global__ __launch_bounds__(32, 1) void haar_prep5_kernel(
    const float* __restrict__ W1, const float* __restrict__ b1,
    const float* __restrict__ W2, const float* __restrict__ b2,
    const float* __restrict__ W3, const float* __restrict__ b3) {
    const int M = blockIdx.x * 32 + threadIdx.x;   // 0..1023

    // ---- stage tail weights into registers (uniform float4 broadcasts) ----
    float w2[64];
#pragma unroll
    for (int i = 0; i < 16; ++i) {
        float4 v = __ldg((const float4*)W2 + i);
        w2[4 * i + 0] = v.x; w2[4 * i + 1] = v.y;
        w2[4 * i + 2] = v.z; w2[4 * i + 3] = v.w;
    }
    float w3[24];
#pragma unroll
    for (int i = 0; i < 6; ++i) {
        float4 v = __ldg((const float4*)W3 + i);
        w3[4 * i + 0] = v.x; w3[4 * i + 1] = v.y;
        w3[4 * i + 2] = v.z; w3[4 * i + 3] = v.w;
    }
    float bb2[8];
    {
        float4 v0 = __ldg((const float4*)b2);
        float4 v1 = __ldg((const float4*)b2 + 1);
        bb2[0] = v0.x; bb2[1] = v0.y; bb2[2] = v0.z; bb2[3] = v0.w;
        bb2[4] = v1.x; bb2[5] = v1.y; bb2[6] = v1.z; bb2[7] = v1.w;
    }
    float bb3[3];
    bb3[0] = __ldg(b3 + 0); bb3[1] = __ldg(b3 + 1); bb3[2] = __ldg(b3 + 2);

    // ---- layer 1: 10 Haar levels, 8 accumulators ----
    float P[8];
    {
        float4 v0 = __ldg((const float4*)b1);
        float4 v1 = __ldg((const float4*)b1 + 1);
        P[0] = v0.x; P[1] = v0.y; P[2] = v0.z; P[3] = v0.w;
        P[4] = v1.x; P[5] = v1.y; P[6] = v1.z; P[7] = v1.w;
    }
#pragma unroll
    for (int j = 0; j < 10; ++j) {
        int idx = (1 << j) - 1 + (M >> (10 - j));
        float s = ((M >> (9 - j)) & 1) ? -1.0f : 1.0f;
        const float4* row = (const float4*)(W1 + idx * 8);
        float4 a = __ldg(row);
        float4 c = __ldg(row + 1);
        P[0] = fmaf(s, a.x, P[0]); P[1] = fmaf(s, a.y, P[1]);
        P[2] = fmaf(s, a.z, P[2]); P[3] = fmaf(s, a.w, P[3]);
        P[4] = fmaf(s, c.x, P[4]); P[5] = fmaf(s, c.y, P[5]);
        P[6] = fmaf(s, c.z, P[6]); P[7] = fmaf(s, c.w, P[7]);
    }
#pragma unroll
    for (int h = 0; h < 8; ++h) P[h] = fmaxf(P[h], 0.0f);

    // ---- layer 2 ----
    float h2[8];
#pragma unroll
    for (int k = 0; k < 8; ++k) h2[k] = bb2[k];
#pragma unroll
    for (int h = 0; h < 8; ++h) {
        float x = P[h];
#pragma unroll
        for (int k = 0; k < 8; ++k) h2[k] = fmaf(x, w2[h * 8 + k], h2[k]);
    }
#pragma unroll
    for (int k = 0; k < 8; ++k) h2[k] = fmaxf(h2[k], 0.0f);

    // ---- layer 3 ----
    float o0 = bb3[0], o1 = bb3[1], o2 = bb3[2];
#pragma unroll
    for (int k = 0; k < 8; ++k) {
        float x = h2[k];
        o0 = fmaf(x, w3[k * 3 + 0], o0);
        o1 = fmaf(x, w3[k * 3 + 1], o1);
        o2 = fmaf(x, w3[k * 3 + 2], o2);
    }
    g_lut[M] = make_float4(o0, o1, o2, 0.0f);
}

__global__ __launch_bounds__(256, 1) void haar_apply5_kernel(
    const float4* __restrict__ t4, float4* __restrict__ out4, int n4) {
    __shared__ float4 lut[1024];   // 16 KB

    const int tid = threadIdx.x;
    const int g   = blockIdx.x * 256 + tid;

    // prefetch t while the LUT copy is in flight
    float4 tv = (g < n4) ? __ldg(t4 + g) : make_float4(0.f, 0.f, 0.f, 0.f);

    // copy global LUT -> SMEM: 4 coalesced float4 loads per thread
#pragma unroll
    for (int i = 0; i < 4; ++i) {
        lut[tid + 256 * i] = g_lut[tid + 256 * i];
    }
    __syncthreads();

    if (g < n4) {
        unsigned m0 = min((unsigned)(int)(tv.x * 1024.0f), 1023u);
        unsigned m1 = min((unsigned)(int)(tv.y * 1024.0f), 1023u);
        unsigned m2 = min((unsigned)(int)(tv.z * 1024.0f), 1023u);
        unsigned m3 = min((unsigned)(int)(tv.w * 1024.0f), 1023u);

        float4 r0 = lut[m0];
        float4 r1 = lut[m1];
        float4 r2 = lut[m2];
        float4 r3 = lut[m3];

        out4[g * 3 + 0] = make_float4(r0.x, r0.y, r0.z, r1.x);
        out4[g * 3 + 1] = make_float4(r1.y, r1.z, r2.x, r2.y);
        out4[g * 3 + 2] = make_float4(r2.z, r3.x, r3.y, r3.z);
    }
}

extern "C" void kernel_launch(void* const* d_in, const int* in_sizes, int n_in,
                              void* d_out, int out_size) {
    const float* t  = (const float*)d_in[0];
    const float* W1 = (const float*)d_in[1];
    const float* b1 = (const float*)d_in[2];
    const float* W2 = (const float*)d_in[3];
    const float* b2 = (const float*)d_in[4];
    const float* W3 = (const float*)d_in[5];
    const float* b3 = (const float*)d_in[6];
    float* out = (float*)d_out;

    int n  = in_sizes[0];            // B*T = 131072
    int n4 = n / 4;                  // 32768 float4 samples

    haar_prep5_kernel<<<32, 32>>>(W1, b1, W2, b2, W3, b3);
    haar_apply5_kernel<<<(n4 + 255) / 256, 256>>>(
        (const float4*)t, (float4*)out, n4);
}